// round 1
// baseline (speedup 1.0000x reference)
#include <cuda_runtime.h>
#include <cuda_bf16.h>
#include <math.h>

// Problem constants (hardcoded from reference)
#define BATCH 2
#define SEQ   2048
#define CDIM  1024
#define NHEAD 16
#define HDIM  64
#define C3    (3*CDIM)          // 3072
#define MROWS (BATCH*SEQ)       // 4096

// Scratch (no cudaMalloc allowed)
__device__ float g_qkv[(size_t)MROWS * C3];     // [B,T,3,H,D]  ~48 MB
__device__ float g_attn[(size_t)MROWS * CDIM];  // [B,T,C]      ~16 MB

// ---------------------------------------------------------------------------
// SGEMM with bias: C[M,N] = A[M,K] @ B[K,N] + bias[N]
// BM=BN=128, BK=8, 256 threads, 8x8 per-thread microtile.
// Requires M%128==0, N%128==0, K%8==0 (true for all our shapes).
// ---------------------------------------------------------------------------
__global__ __launch_bounds__(256)
void sgemm_bias_kernel(const float* __restrict__ A,
                       const float* __restrict__ B,
                       const float* __restrict__ bias,
                       float* __restrict__ C,
                       int M, int N, int K)
{
    const int BM = 128, BN = 128, BK = 8;
    __shared__ float As[BK][BM];
    __shared__ float Bs[BK][BN];

    const int tid     = threadIdx.x;
    const int rowbase = blockIdx.y * BM;
    const int colbase = blockIdx.x * BN;

    const int aRow = tid >> 1;              // 0..127
    const int aCol = (tid & 1) << 2;        // 0 or 4
    const int bRow = tid >> 5;              // 0..7
    const int bCol = (tid & 31) << 2;       // 0..124

    const int trow = (tid >> 4) << 3;       // (tid/16)*8
    const int tcol = (tid & 15) << 3;       // (tid%16)*8

    float acc[8][8];
    #pragma unroll
    for (int i = 0; i < 8; i++)
        #pragma unroll
        for (int j = 0; j < 8; j++) acc[i][j] = 0.f;

    for (int k0 = 0; k0 < K; k0 += BK) {
        // Load A tile (BMxBK), stored transposed As[k][m]
        float4 av = *(const float4*)(A + (size_t)(rowbase + aRow) * K + k0 + aCol);
        As[aCol + 0][aRow] = av.x;
        As[aCol + 1][aRow] = av.y;
        As[aCol + 2][aRow] = av.z;
        As[aCol + 3][aRow] = av.w;
        // Load B tile (BKxBN)
        *(float4*)(&Bs[bRow][bCol]) =
            *(const float4*)(B + (size_t)(k0 + bRow) * N + colbase + bCol);
        __syncthreads();

        #pragma unroll
        for (int kk = 0; kk < BK; kk++) {
            float ar[8], br[8];
            *(float4*)(ar)     = *(const float4*)(&As[kk][trow]);
            *(float4*)(ar + 4) = *(const float4*)(&As[kk][trow + 4]);
            *(float4*)(br)     = *(const float4*)(&Bs[kk][tcol]);
            *(float4*)(br + 4) = *(const float4*)(&Bs[kk][tcol + 4]);
            #pragma unroll
            for (int i = 0; i < 8; i++)
                #pragma unroll
                for (int j = 0; j < 8; j++)
                    acc[i][j] += ar[i] * br[j];
        }
        __syncthreads();
    }

    #pragma unroll
    for (int i = 0; i < 8; i++) {
        float* cp = C + (size_t)(rowbase + trow + i) * N + colbase + tcol;
        const float* bp = bias + colbase + tcol;
        #pragma unroll
        for (int j = 0; j < 8; j++) cp[j] = acc[i][j] + bp[j];
    }
}

// ---------------------------------------------------------------------------
// Flash attention (fp32, causal). One block = 128 q rows of one (b,h).
// Each thread owns one q row: q[64] in regs, O[64] accumulator, online
// softmax with one rescale per 32-key tile.
// qkv layout: [B, T, 3, H, D] (i.e. row stride C3=3072; q at +0, k at +1024,
// v at +2048 within a (b,t) row; head offset h*64).
// ---------------------------------------------------------------------------
#define QROWS 128
#define KTILE 32

__global__ __launch_bounds__(QROWS)
void attn_kernel(const float* __restrict__ qkv, float* __restrict__ out)
{
    const int qt  = blockIdx.x;      // q tile
    const int h   = blockIdx.y;      // head
    const int b   = blockIdx.z;      // batch
    const int tid = threadIdx.x;
    const int qrow = qt * QROWS + tid;   // global q position (< SEQ)
    const float scale = 0.125f;          // 1/sqrt(64)

    __shared__ float Ks[KTILE][HDIM];    // 8 KB
    __shared__ float Vs[KTILE][HDIM];    // 8 KB

    // Load this thread's q row into registers
    float q[HDIM];
    {
        const float4* qp = (const float4*)(qkv + (size_t)(b * SEQ + qrow) * C3 + h * HDIM);
        #pragma unroll
        for (int i = 0; i < HDIM / 4; i++) {
            float4 t = qp[i];
            q[4*i+0] = t.x; q[4*i+1] = t.y; q[4*i+2] = t.z; q[4*i+3] = t.w;
        }
    }

    float m = -INFINITY, l = 0.f;
    float O[HDIM];
    #pragma unroll
    for (int d = 0; d < HDIM; d++) O[d] = 0.f;

    const int nk = qt * QROWS + QROWS;   // keys in [0, nk) can be relevant

    for (int k0 = 0; k0 < nk; k0 += KTILE) {
        __syncthreads();   // previous tile fully consumed
        // Cooperative load of K and V tiles (KTILE x 64 floats each)
        for (int i = tid; i < KTILE * (HDIM / 4); i += QROWS) {
            int r = i >> 4;          // key row in tile
            int c = i & 15;          // float4 index
            const float4* kp = (const float4*)(qkv + (size_t)(b * SEQ + k0 + r) * C3 + CDIM  + h * HDIM);
            const float4* vp = (const float4*)(qkv + (size_t)(b * SEQ + k0 + r) * C3 + 2*CDIM + h * HDIM);
            ((float4*)Ks[r])[c] = kp[c];
            ((float4*)Vs[r])[c] = vp[c];
        }
        __syncthreads();

        // Pass 1: scores for this tile + tile max
        float s[KTILE];
        float tmax = -INFINITY;
        #pragma unroll
        for (int j = 0; j < KTILE; j++) {
            float acc = 0.f;
            #pragma unroll
            for (int d4 = 0; d4 < HDIM / 4; d4++) {
                float4 kk = ((const float4*)Ks[j])[d4];
                acc += q[4*d4+0] * kk.x + q[4*d4+1] * kk.y
                     + q[4*d4+2] * kk.z + q[4*d4+3] * kk.w;
            }
            acc *= scale;
            if (k0 + j > qrow) acc = -INFINITY;   // causal mask
            s[j] = acc;
            tmax = fmaxf(tmax, acc);
        }

        // Rescale once per tile
        float newm = fmaxf(m, tmax);
        float corr = __expf(m - newm);            // 0 when m == -inf
        l *= corr;
        #pragma unroll
        for (int d = 0; d < HDIM; d++) O[d] *= corr;

        // Pass 2: accumulate P·V
        #pragma unroll
        for (int j = 0; j < KTILE; j++) {
            float p = __expf(s[j] - newm);        // 0 for masked entries
            l += p;
            #pragma unroll
            for (int d4 = 0; d4 < HDIM / 4; d4++) {
                float4 vv = ((const float4*)Vs[j])[d4];
                O[4*d4+0] += p * vv.x; O[4*d4+1] += p * vv.y;
                O[4*d4+2] += p * vv.z; O[4*d4+3] += p * vv.w;
            }
        }
        m = newm;
    }

    // Write normalized output: g_attn[b, t, h*64 + d]  (layout [B,T,C])
    const float inv = 1.f / l;
    float4* op = (float4*)(out + (size_t)(b * SEQ + qrow) * CDIM + h * HDIM);
    #pragma unroll
    for (int i = 0; i < HDIM / 4; i++) {
        float4 t;
        t.x = O[4*i+0] * inv; t.y = O[4*i+1] * inv;
        t.z = O[4*i+2] * inv; t.w = O[4*i+3] * inv;
        op[i] = t;
    }
}

// ---------------------------------------------------------------------------
// Launch
// ---------------------------------------------------------------------------
extern "C" void kernel_launch(void* const* d_in, const int* in_sizes, int n_in,
                              void* d_out, int out_size)
{
    const float* x    = (const float*)d_in[0];
    const float* Wqkv = (const float*)d_in[1];
    const float* bqkv = (const float*)d_in[2];
    const float* Wout = (const float*)d_in[3];
    const float* bout = (const float*)d_in[4];
    float* out = (float*)d_out;

    float* qkv  = nullptr;
    float* attn = nullptr;
    cudaGetSymbolAddress((void**)&qkv,  g_qkv);
    cudaGetSymbolAddress((void**)&attn, g_attn);

    // 1) QKV projection: [4096,1024] @ [1024,3072] + bias
    {
        dim3 grid(C3 / 128, MROWS / 128);
        sgemm_bias_kernel<<<grid, 256>>>(x, Wqkv, bqkv, qkv, MROWS, C3, CDIM);
    }
    // 2) Causal flash attention -> g_attn [B,T,C]
    {
        dim3 grid(SEQ / QROWS, NHEAD, BATCH);
        attn_kernel<<<grid, QROWS>>>(qkv, attn);
    }
    // 3) Output projection: [4096,1024] @ [1024,1024] + bias -> d_out
    {
        dim3 grid(CDIM / 128, MROWS / 128);
        sgemm_bias_kernel<<<grid, 256>>>(attn, Wout, bout, out, MROWS, CDIM, CDIM);
    }
}

// round 3
// speedup vs baseline: 1.3616x; 1.3616x over previous
#include <cuda_runtime.h>
#include <cuda_bf16.h>
#include <math.h>
#include <stdint.h>

// Problem constants
#define BATCH 2
#define SEQ   2048
#define CDIM  1024
#define NHEAD 16
#define HDIM  64
#define C3    (3*CDIM)          // 3072
#define MROWS (BATCH*SEQ)       // 4096

// Scratch (no cudaMalloc allowed)
__device__ float g_qkv[(size_t)MROWS * C3];     // [B,T,3,H,D]
__device__ float g_attn[(size_t)MROWS * CDIM];  // [B,T,C]

__device__ __forceinline__ uint32_t f2tf32(float f) {
    uint32_t r;
    asm("cvt.rna.tf32.f32 %0, %1;" : "=r"(r) : "f"(f));
    return r;
}

__device__ __forceinline__ void mma_tf32(float c[4], const uint32_t a[4], const uint32_t b[2]) {
    asm volatile(
        "mma.sync.aligned.m16n8k8.row.col.f32.tf32.tf32.f32 "
        "{%0,%1,%2,%3}, {%4,%5,%6,%7}, {%8,%9}, {%0,%1,%2,%3};"
        : "+f"(c[0]), "+f"(c[1]), "+f"(c[2]), "+f"(c[3])
        : "r"(a[0]), "r"(a[1]), "r"(a[2]), "r"(a[3]), "r"(b[0]), "r"(b[1]));
}

// ---------------------------------------------------------------------------
// tf32 mma.sync GEMM + bias: C[M,N] = A[M,K] @ B[K,N] + bias[N]
// CTA tile 128x128, BK=32. 8 warps as 2(M) x 4(N); warp tile 64x32.
// Smem: As[128][36] (row-major, pad 4 -> conflict-free frag loads, 16B-aligned
// float4 stores), Bs[32][136] (row-major, pad 8 -> conflict-free frag loads).
// Double-buffered, one __syncthreads per K-chunk.
// Requires M%128==0, N%128==0, K%32==0.
// ---------------------------------------------------------------------------
#define GBM 128
#define GBN 128
#define GBK 32
#define A_STRIDE 36
#define B_STRIDE 136
#define A_FLOATS (GBM * A_STRIDE)      // 4608
#define B_FLOATS (GBK * B_STRIDE)      // 4352
#define BUF_FLOATS (A_FLOATS + B_FLOATS)
#define GEMM_SMEM (2 * BUF_FLOATS * 4) // 71680 bytes

__global__ __launch_bounds__(256)
void gemm_tc_kernel(const float* __restrict__ A,
                    const float* __restrict__ B,
                    const float* __restrict__ bias,
                    float* __restrict__ C,
                    int M, int N, int K)
{
    extern __shared__ float smem[];
    const int tid = threadIdx.x;
    const int wid = tid >> 5;
    const int l   = tid & 31;
    const int warpM = wid >> 2;          // 0..1
    const int warpN = wid & 3;           // 0..3
    const int rowbase = blockIdx.y * GBM;
    const int colbase = blockIdx.x * GBN;

    float* As[2] = { smem,              smem + BUF_FLOATS };
    float* Bs[2] = { smem + A_FLOATS,   smem + BUF_FLOATS + A_FLOATS };

    float acc[4][4][4];
    #pragma unroll
    for (int i = 0; i < 4; i++)
        #pragma unroll
        for (int j = 0; j < 4; j++)
            #pragma unroll
            for (int q = 0; q < 4; q++) acc[i][j][q] = 0.f;

    // Global-load per-thread mapping (4 float4 each for A and B per chunk)
    const int ar = tid >> 3;             // A row within tile for it=0 (stride 32 rows/iter)
    const int ac = (tid & 7) * 4;        // A col
    const int bk = tid >> 5;             // B k-row for it=0 (stride 8 rows/iter)
    const int bn = (tid & 31) * 4;       // B col

    const int S = K / GBK;

    float4 areg[4], breg[4];

    // Prologue: load chunk 0 and store to buffer 0
    #pragma unroll
    for (int it = 0; it < 4; it++) {
        areg[it] = *(const float4*)(A + (size_t)(rowbase + it * 32 + ar) * K + ac);
        breg[it] = *(const float4*)(B + (size_t)(it * 8 + bk) * N + colbase + bn);
    }
    #pragma unroll
    for (int it = 0; it < 4; it++) {
        uint4 ta; ta.x = f2tf32(areg[it].x); ta.y = f2tf32(areg[it].y);
                  ta.z = f2tf32(areg[it].z); ta.w = f2tf32(areg[it].w);
        *(uint4*)(As[0] + (it * 32 + ar) * A_STRIDE + ac) = ta;
        uint4 tb; tb.x = f2tf32(breg[it].x); tb.y = f2tf32(breg[it].y);
                  tb.z = f2tf32(breg[it].z); tb.w = f2tf32(breg[it].w);
        *(uint4*)(Bs[0] + (it * 8 + bk) * B_STRIDE + bn) = tb;
    }
    __syncthreads();

    const int arow0 = warpM * 64 + (l >> 2);    // fragment row base
    const int bcol0 = warpN * 32 + (l >> 2);    // fragment col base
    const int kfrag = (l & 3);

    for (int s = 0; s < S; s++) {
        const int cur = s & 1;
        const int nxt = cur ^ 1;

        // Prefetch next chunk into registers
        if (s + 1 < S) {
            const int k0 = (s + 1) * GBK;
            #pragma unroll
            for (int it = 0; it < 4; it++) {
                areg[it] = *(const float4*)(A + (size_t)(rowbase + it * 32 + ar) * K + k0 + ac);
                breg[it] = *(const float4*)(B + (size_t)(k0 + it * 8 + bk) * N + colbase + bn);
            }
        }

        // Compute on current buffer
        const float* as = As[cur];
        const float* bs = Bs[cur];
        #pragma unroll
        for (int ks = 0; ks < 4; ks++) {
            const int kk = ks * 8 + kfrag;
            uint32_t af[4][4], bf[4][2];
            #pragma unroll
            for (int i = 0; i < 4; i++) {
                const int r = arow0 + i * 16;
                af[i][0] = __float_as_uint(as[(r    ) * A_STRIDE + kk    ]);
                af[i][1] = __float_as_uint(as[(r + 8) * A_STRIDE + kk    ]);
                af[i][2] = __float_as_uint(as[(r    ) * A_STRIDE + kk + 4]);
                af[i][3] = __float_as_uint(as[(r + 8) * A_STRIDE + kk + 4]);
            }
            #pragma unroll
            for (int j = 0; j < 4; j++) {
                const int n = bcol0 + j * 8;
                bf[j][0] = __float_as_uint(bs[(ks * 8 + kfrag    ) * B_STRIDE + n]);
                bf[j][1] = __float_as_uint(bs[(ks * 8 + kfrag + 4) * B_STRIDE + n]);
            }
            #pragma unroll
            for (int i = 0; i < 4; i++)
                #pragma unroll
                for (int j = 0; j < 4; j++)
                    mma_tf32(acc[i][j], af[i], bf[j]);
        }

        // Store prefetched chunk into the other buffer
        if (s + 1 < S) {
            #pragma unroll
            for (int it = 0; it < 4; it++) {
                uint4 ta; ta.x = f2tf32(areg[it].x); ta.y = f2tf32(areg[it].y);
                          ta.z = f2tf32(areg[it].z); ta.w = f2tf32(areg[it].w);
                *(uint4*)(As[nxt] + (it * 32 + ar) * A_STRIDE + ac) = ta;
                uint4 tb; tb.x = f2tf32(breg[it].x); tb.y = f2tf32(breg[it].y);
                          tb.z = f2tf32(breg[it].z); tb.w = f2tf32(breg[it].w);
                *(uint4*)(Bs[nxt] + (it * 8 + bk) * B_STRIDE + bn) = tb;
            }
        }
        __syncthreads();
    }

    // Epilogue: c-frag layout m16n8: c0 (r, 2c), c1 (r, 2c+1), c2/c3 at r+8
    const int erow = rowbase + warpM * 64 + (l >> 2);
    const int ecol = colbase + warpN * 32 + 2 * (l & 3);
    #pragma unroll
    for (int i = 0; i < 4; i++) {
        #pragma unroll
        for (int j = 0; j < 4; j++) {
            const int r0 = erow + i * 16;
            const int c0 = ecol + j * 8;
            const float b0 = bias[c0], b1 = bias[c0 + 1];
            float2 v0 = { acc[i][j][0] + b0, acc[i][j][1] + b1 };
            float2 v1 = { acc[i][j][2] + b0, acc[i][j][3] + b1 };
            *(float2*)(C + (size_t)r0 * N + c0)       = v0;
            *(float2*)(C + (size_t)(r0 + 8) * N + c0) = v1;
        }
    }
}

// ---------------------------------------------------------------------------
// Flash attention (fp32, causal) — unchanged (R4 target).
// ---------------------------------------------------------------------------
#define QROWS 128
#define KTILE 32

__global__ __launch_bounds__(QROWS)
void attn_kernel(const float* __restrict__ qkv, float* __restrict__ out)
{
    const int qt  = blockIdx.x;
    const int h   = blockIdx.y;
    const int b   = blockIdx.z;
    const int tid = threadIdx.x;
    const int qrow = qt * QROWS + tid;
    const float scale = 0.125f;

    __shared__ float Ks[KTILE][HDIM];
    __shared__ float Vs[KTILE][HDIM];

    float q[HDIM];
    {
        const float4* qp = (const float4*)(qkv + (size_t)(b * SEQ + qrow) * C3 + h * HDIM);
        #pragma unroll
        for (int i = 0; i < HDIM / 4; i++) {
            float4 t = qp[i];
            q[4*i+0] = t.x; q[4*i+1] = t.y; q[4*i+2] = t.z; q[4*i+3] = t.w;
        }
    }

    float m = -INFINITY, lsum = 0.f;
    float O[HDIM];
    #pragma unroll
    for (int d = 0; d < HDIM; d++) O[d] = 0.f;

    const int nk = qt * QROWS + QROWS;

    for (int k0 = 0; k0 < nk; k0 += KTILE) {
        __syncthreads();
        for (int i = tid; i < KTILE * (HDIM / 4); i += QROWS) {
            int r = i >> 4;
            int c = i & 15;
            const float4* kp = (const float4*)(qkv + (size_t)(b * SEQ + k0 + r) * C3 + CDIM  + h * HDIM);
            const float4* vp = (const float4*)(qkv + (size_t)(b * SEQ + k0 + r) * C3 + 2*CDIM + h * HDIM);
            ((float4*)Ks[r])[c] = kp[c];
            ((float4*)Vs[r])[c] = vp[c];
        }
        __syncthreads();

        float s[KTILE];
        float tmax = -INFINITY;
        #pragma unroll
        for (int j = 0; j < KTILE; j++) {
            float a = 0.f;
            #pragma unroll
            for (int d4 = 0; d4 < HDIM / 4; d4++) {
                float4 kk = ((const float4*)Ks[j])[d4];
                a += q[4*d4+0] * kk.x + q[4*d4+1] * kk.y
                   + q[4*d4+2] * kk.z + q[4*d4+3] * kk.w;
            }
            a *= scale;
            if (k0 + j > qrow) a = -INFINITY;
            s[j] = a;
            tmax = fmaxf(tmax, a);
        }

        float newm = fmaxf(m, tmax);
        float corr = __expf(m - newm);
        lsum *= corr;
        #pragma unroll
        for (int d = 0; d < HDIM; d++) O[d] *= corr;

        #pragma unroll
        for (int j = 0; j < KTILE; j++) {
            float p = __expf(s[j] - newm);
            lsum += p;
            #pragma unroll
            for (int d4 = 0; d4 < HDIM / 4; d4++) {
                float4 vv = ((const float4*)Vs[j])[d4];
                O[4*d4+0] += p * vv.x; O[4*d4+1] += p * vv.y;
                O[4*d4+2] += p * vv.z; O[4*d4+3] += p * vv.w;
            }
        }
        m = newm;
    }

    const float inv = 1.f / lsum;
    float4* op = (float4*)(out + (size_t)(b * SEQ + qrow) * CDIM + h * HDIM);
    #pragma unroll
    for (int i = 0; i < HDIM / 4; i++) {
        float4 t;
        t.x = O[4*i+0] * inv; t.y = O[4*i+1] * inv;
        t.z = O[4*i+2] * inv; t.w = O[4*i+3] * inv;
        op[i] = t;
    }
}

// ---------------------------------------------------------------------------
// Launch
// ---------------------------------------------------------------------------
extern "C" void kernel_launch(void* const* d_in, const int* in_sizes, int n_in,
                              void* d_out, int out_size)
{
    const float* x    = (const float*)d_in[0];
    const float* Wqkv = (const float*)d_in[1];
    const float* bqkv = (const float*)d_in[2];
    const float* Wout = (const float*)d_in[3];
    const float* bout = (const float*)d_in[4];
    float* out = (float*)d_out;

    float* qkv  = nullptr;
    float* attn = nullptr;
    cudaGetSymbolAddress((void**)&qkv,  g_qkv);
    cudaGetSymbolAddress((void**)&attn, g_attn);

    static bool attr_set = false;
    if (!attr_set) {
        cudaFuncSetAttribute(gemm_tc_kernel, cudaFuncAttributeMaxDynamicSharedMemorySize, GEMM_SMEM);
        attr_set = true;
    }

    // 1) QKV projection: [4096,1024] @ [1024,3072] + bias
    {
        dim3 grid(C3 / GBN, MROWS / GBM);
        gemm_tc_kernel<<<grid, 256, GEMM_SMEM>>>(x, Wqkv, bqkv, qkv, MROWS, C3, CDIM);
    }
    // 2) Causal flash attention -> g_attn [B,T,C]
    {
        dim3 grid(SEQ / QROWS, NHEAD, BATCH);
        attn_kernel<<<grid, QROWS>>>(qkv, attn);
    }
    // 3) Output projection: [4096,1024] @ [1024,1024] + bias -> d_out
    {
        dim3 grid(CDIM / GBN, MROWS / GBM);
        gemm_tc_kernel<<<grid, 256, GEMM_SMEM>>>(attn, Wout, bout, out, MROWS, CDIM, CDIM);
    }
}

// round 4
// speedup vs baseline: 3.3861x; 2.4868x over previous
#include <cuda_runtime.h>
#include <cuda_bf16.h>
#include <math.h>
#include <stdint.h>

// Problem constants
#define BATCH 2
#define SEQ   2048
#define CDIM  1024
#define NHEAD 16
#define HDIM  64
#define C3    (3*CDIM)          // 3072
#define MROWS (BATCH*SEQ)       // 4096

// Scratch (no cudaMalloc allowed)
__device__ float g_qkv[(size_t)MROWS * C3];     // [B,T,3,H,D]
__device__ float g_attn[(size_t)MROWS * CDIM];  // [B,T,C]

__device__ __forceinline__ uint32_t f2tf32(float f) {
    uint32_t r;
    asm("cvt.rna.tf32.f32 %0, %1;" : "=r"(r) : "f"(f));
    return r;
}
__device__ __forceinline__ float fexp2(float x) {
    float y;
    asm("ex2.approx.f32 %0, %1;" : "=f"(y) : "f"(x));
    return y;
}

__device__ __forceinline__ void mma_tf32(float c[4], const uint32_t a[4], const uint32_t b[2]) {
    asm volatile(
        "mma.sync.aligned.m16n8k8.row.col.f32.tf32.tf32.f32 "
        "{%0,%1,%2,%3}, {%4,%5,%6,%7}, {%8,%9}, {%0,%1,%2,%3};"
        : "+f"(c[0]), "+f"(c[1]), "+f"(c[2]), "+f"(c[3])
        : "r"(a[0]), "r"(a[1]), "r"(a[2]), "r"(a[3]), "r"(b[0]), "r"(b[1]));
}

// ---------------------------------------------------------------------------
// tf32 mma.sync GEMM + bias (unchanged from R3: 109 TF/s)
// ---------------------------------------------------------------------------
#define GBM 128
#define GBN 128
#define GBK 32
#define A_STRIDE 36
#define B_STRIDE 136
#define A_FLOATS (GBM * A_STRIDE)
#define B_FLOATS (GBK * B_STRIDE)
#define BUF_FLOATS (A_FLOATS + B_FLOATS)
#define GEMM_SMEM (2 * BUF_FLOATS * 4)

__global__ __launch_bounds__(256)
void gemm_tc_kernel(const float* __restrict__ A,
                    const float* __restrict__ B,
                    const float* __restrict__ bias,
                    float* __restrict__ C,
                    int M, int N, int K)
{
    extern __shared__ float smem[];
    const int tid = threadIdx.x;
    const int wid = tid >> 5;
    const int l   = tid & 31;
    const int warpM = wid >> 2;
    const int warpN = wid & 3;
    const int rowbase = blockIdx.y * GBM;
    const int colbase = blockIdx.x * GBN;

    float* As[2] = { smem,              smem + BUF_FLOATS };
    float* Bs[2] = { smem + A_FLOATS,   smem + BUF_FLOATS + A_FLOATS };

    float acc[4][4][4];
    #pragma unroll
    for (int i = 0; i < 4; i++)
        #pragma unroll
        for (int j = 0; j < 4; j++)
            #pragma unroll
            for (int q = 0; q < 4; q++) acc[i][j][q] = 0.f;

    const int ar = tid >> 3;
    const int ac = (tid & 7) * 4;
    const int bk = tid >> 5;
    const int bn = (tid & 31) * 4;

    const int S = K / GBK;
    float4 areg[4], breg[4];

    #pragma unroll
    for (int it = 0; it < 4; it++) {
        areg[it] = *(const float4*)(A + (size_t)(rowbase + it * 32 + ar) * K + ac);
        breg[it] = *(const float4*)(B + (size_t)(it * 8 + bk) * N + colbase + bn);
    }
    #pragma unroll
    for (int it = 0; it < 4; it++) {
        uint4 ta; ta.x = f2tf32(areg[it].x); ta.y = f2tf32(areg[it].y);
                  ta.z = f2tf32(areg[it].z); ta.w = f2tf32(areg[it].w);
        *(uint4*)(As[0] + (it * 32 + ar) * A_STRIDE + ac) = ta;
        uint4 tb; tb.x = f2tf32(breg[it].x); tb.y = f2tf32(breg[it].y);
                  tb.z = f2tf32(breg[it].z); tb.w = f2tf32(breg[it].w);
        *(uint4*)(Bs[0] + (it * 8 + bk) * B_STRIDE + bn) = tb;
    }
    __syncthreads();

    const int arow0 = warpM * 64 + (l >> 2);
    const int bcol0 = warpN * 32 + (l >> 2);
    const int kfrag = (l & 3);

    for (int s = 0; s < S; s++) {
        const int cur = s & 1;
        const int nxt = cur ^ 1;

        if (s + 1 < S) {
            const int k0 = (s + 1) * GBK;
            #pragma unroll
            for (int it = 0; it < 4; it++) {
                areg[it] = *(const float4*)(A + (size_t)(rowbase + it * 32 + ar) * K + k0 + ac);
                breg[it] = *(const float4*)(B + (size_t)(k0 + it * 8 + bk) * N + colbase + bn);
            }
        }

        const float* as = As[cur];
        const float* bs = Bs[cur];
        #pragma unroll
        for (int ks = 0; ks < 4; ks++) {
            const int kk = ks * 8 + kfrag;
            uint32_t af[4][4], bf[4][2];
            #pragma unroll
            for (int i = 0; i < 4; i++) {
                const int r = arow0 + i * 16;
                af[i][0] = __float_as_uint(as[(r    ) * A_STRIDE + kk    ]);
                af[i][1] = __float_as_uint(as[(r + 8) * A_STRIDE + kk    ]);
                af[i][2] = __float_as_uint(as[(r    ) * A_STRIDE + kk + 4]);
                af[i][3] = __float_as_uint(as[(r + 8) * A_STRIDE + kk + 4]);
            }
            #pragma unroll
            for (int j = 0; j < 4; j++) {
                const int n = bcol0 + j * 8;
                bf[j][0] = __float_as_uint(bs[(ks * 8 + kfrag    ) * B_STRIDE + n]);
                bf[j][1] = __float_as_uint(bs[(ks * 8 + kfrag + 4) * B_STRIDE + n]);
            }
            #pragma unroll
            for (int i = 0; i < 4; i++)
                #pragma unroll
                for (int j = 0; j < 4; j++)
                    mma_tf32(acc[i][j], af[i], bf[j]);
        }

        if (s + 1 < S) {
            #pragma unroll
            for (int it = 0; it < 4; it++) {
                uint4 ta; ta.x = f2tf32(areg[it].x); ta.y = f2tf32(areg[it].y);
                          ta.z = f2tf32(areg[it].z); ta.w = f2tf32(areg[it].w);
                *(uint4*)(As[nxt] + (it * 32 + ar) * A_STRIDE + ac) = ta;
                uint4 tb; tb.x = f2tf32(breg[it].x); tb.y = f2tf32(breg[it].y);
                          tb.z = f2tf32(breg[it].z); tb.w = f2tf32(breg[it].w);
                *(uint4*)(Bs[nxt] + (it * 8 + bk) * B_STRIDE + bn) = tb;
            }
        }
        __syncthreads();
    }

    const int erow = rowbase + warpM * 64 + (l >> 2);
    const int ecol = colbase + warpN * 32 + 2 * (l & 3);
    #pragma unroll
    for (int i = 0; i < 4; i++) {
        #pragma unroll
        for (int j = 0; j < 4; j++) {
            const int r0 = erow + i * 16;
            const int c0 = ecol + j * 8;
            const float b0 = bias[c0], b1 = bias[c0 + 1];
            float2 v0 = { acc[i][j][0] + b0, acc[i][j][1] + b1 };
            float2 v1 = { acc[i][j][2] + b0, acc[i][j][3] + b1 };
            *(float2*)(C + (size_t)r0 * N + c0)       = v0;
            *(float2*)(C + (size_t)(r0 + 8) * N + c0) = v1;
        }
    }
}

// ---------------------------------------------------------------------------
// Tensor-core flash attention (tf32 mma, causal, online softmax).
// CTA = 128 q rows of one (b,h); 8 warps x 16 rows. K-tile = 64 keys.
// Ksm stride 68, Vsm stride 72, per-warp P stage stride 68 (all conflict-free
// for the fragment access patterns). Softmax in base-2 with scale*log2e folded.
// ---------------------------------------------------------------------------
#define AQ 128
#define AK 64
#define KS_STRIDE 68
#define VS_STRIDE 72
#define PS_STRIDE 68
#define KS_FLOATS (AK * KS_STRIDE)                 // 4352
#define VS_FLOATS (AK * VS_STRIDE)                 // 4608
#define PS_FLOATS (8 * 16 * PS_STRIDE)             // 8704
#define ATTN_SMEM ((KS_FLOATS + VS_FLOATS + PS_FLOATS) * 4)  // 70656 B

__global__ __launch_bounds__(256)
void attn_tc_kernel(const float* __restrict__ qkv, float* __restrict__ out)
{
    extern __shared__ float sm[];
    float* Ksm = sm;
    float* Vsm = sm + KS_FLOATS;
    float* Psm = sm + KS_FLOATS + VS_FLOATS;

    const int qtile = blockIdx.x;
    const int h   = blockIdx.y;
    const int b   = blockIdx.z;
    const int tid = threadIdx.x;
    const int wid = tid >> 5;
    const int l   = tid & 31;
    const int g   = l >> 2;            // group id (row within fragment)
    const int t   = l & 3;             // thread-in-group (k / col pairs)
    const int qb  = qtile * AQ;
    const int rg  = qb + wid * 16 + g; // this thread's q row (also rg+8)

    const float SC = 0.18033688011112042f;   // (1/sqrt(64)) * log2(e)
    float* Pw = Psm + wid * (16 * PS_STRIDE);

    // Q fragments, register-resident for the whole CTA lifetime
    uint32_t qa[8][4];
    {
        const float* Qr  = qkv + (size_t)(b * SEQ + rg    ) * C3 + h * HDIM;
        const float* Qr8 = qkv + (size_t)(b * SEQ + rg + 8) * C3 + h * HDIM;
        #pragma unroll
        for (int ks = 0; ks < 8; ks++) {
            qa[ks][0] = f2tf32(Qr [ks * 8 + t]);
            qa[ks][1] = f2tf32(Qr8[ks * 8 + t]);
            qa[ks][2] = f2tf32(Qr [ks * 8 + t + 4]);
            qa[ks][3] = f2tf32(Qr8[ks * 8 + t + 4]);
        }
    }

    float O[8][4];
    #pragma unroll
    for (int nb = 0; nb < 8; nb++)
        #pragma unroll
        for (int q = 0; q < 4; q++) O[nb][q] = 0.f;
    float m0 = -INFINITY, m1 = -INFINITY, l0 = 0.f, l1 = 0.f;

    const int nk = qb + AQ;

    for (int kb = 0; kb < nk; kb += AK) {
        __syncthreads();
        // Cooperative K/V tile load (64 x 64 each), tf32-rounded
        #pragma unroll
        for (int it = 0; it < 4; it++) {
            const int idx = it * 256 + tid;
            const int r = idx >> 4;
            const int c = (idx & 15) * 4;
            const size_t rowoff = (size_t)(b * SEQ + kb + r) * C3 + h * HDIM + c;
            float4 kv = *(const float4*)(qkv + rowoff + CDIM);
            uint4 tk; tk.x = f2tf32(kv.x); tk.y = f2tf32(kv.y);
                      tk.z = f2tf32(kv.z); tk.w = f2tf32(kv.w);
            *(uint4*)(Ksm + r * KS_STRIDE + c) = tk;
            float4 vv = *(const float4*)(qkv + rowoff + 2 * CDIM);
            uint4 tv; tv.x = f2tf32(vv.x); tv.y = f2tf32(vv.y);
                      tv.z = f2tf32(vv.z); tv.w = f2tf32(vv.w);
            *(uint4*)(Vsm + r * VS_STRIDE + c) = tv;
        }
        __syncthreads();

        // S = Q @ K^T  (per warp: 16 x 64)
        float sc[8][4];
        #pragma unroll
        for (int nb = 0; nb < 8; nb++) {
            sc[nb][0] = 0.f; sc[nb][1] = 0.f; sc[nb][2] = 0.f; sc[nb][3] = 0.f;
            #pragma unroll
            for (int ks = 0; ks < 8; ks++) {
                uint32_t bf[2];
                bf[0] = __float_as_uint(Ksm[(nb * 8 + g) * KS_STRIDE + ks * 8 + t    ]);
                bf[1] = __float_as_uint(Ksm[(nb * 8 + g) * KS_STRIDE + ks * 8 + t + 4]);
                mma_tf32(sc[nb], qa[ks], bf);
            }
        }

        // scale (log2 domain) + causal mask + tile row-max
        float tm0 = -INFINITY, tm1 = -INFINITY;
        #pragma unroll
        for (int nb = 0; nb < 8; nb++) {
            const int k0 = kb + nb * 8 + 2 * t;
            float s0 = sc[nb][0] * SC, s1 = sc[nb][1] * SC;
            float s2 = sc[nb][2] * SC, s3 = sc[nb][3] * SC;
            if (k0     > rg    ) s0 = -INFINITY;
            if (k0 + 1 > rg    ) s1 = -INFINITY;
            if (k0     > rg + 8) s2 = -INFINITY;
            if (k0 + 1 > rg + 8) s3 = -INFINITY;
            sc[nb][0] = s0; sc[nb][1] = s1; sc[nb][2] = s2; sc[nb][3] = s3;
            tm0 = fmaxf(tm0, fmaxf(s0, s1));
            tm1 = fmaxf(tm1, fmaxf(s2, s3));
        }
        tm0 = fmaxf(tm0, __shfl_xor_sync(0xffffffffu, tm0, 1));
        tm0 = fmaxf(tm0, __shfl_xor_sync(0xffffffffu, tm0, 2));
        tm1 = fmaxf(tm1, __shfl_xor_sync(0xffffffffu, tm1, 1));
        tm1 = fmaxf(tm1, __shfl_xor_sync(0xffffffffu, tm1, 2));

        const float nm0 = fmaxf(m0, tm0);
        const float nm1 = fmaxf(m1, tm1);
        const float c0 = fexp2(m0 - nm0);
        const float c1 = fexp2(m1 - nm1);
        l0 *= c0; l1 *= c1;
        #pragma unroll
        for (int nb = 0; nb < 8; nb++) {
            O[nb][0] *= c0; O[nb][1] *= c0;
            O[nb][2] *= c1; O[nb][3] *= c1;
        }
        m0 = nm0; m1 = nm1;

        // p = exp2(s - m); accumulate row sums; stage P (tf32) in warp-private smem
        #pragma unroll
        for (int nb = 0; nb < 8; nb++) {
            float p0 = fexp2(sc[nb][0] - m0);
            float p1 = fexp2(sc[nb][1] - m0);
            float p2 = fexp2(sc[nb][2] - m1);
            float p3 = fexp2(sc[nb][3] - m1);
            l0 += p0 + p1;
            l1 += p2 + p3;
            uint2 u0 = { f2tf32(p0), f2tf32(p1) };
            uint2 u1 = { f2tf32(p2), f2tf32(p3) };
            *(uint2*)(Pw + (g    ) * PS_STRIDE + nb * 8 + 2 * t) = u0;
            *(uint2*)(Pw + (g + 8) * PS_STRIDE + nb * 8 + 2 * t) = u1;
        }
        __syncwarp();

        // O += P @ V
        #pragma unroll
        for (int ks = 0; ks < 8; ks++) {
            uint32_t pa[4];
            pa[0] = __float_as_uint(Pw[(g    ) * PS_STRIDE + ks * 8 + t    ]);
            pa[1] = __float_as_uint(Pw[(g + 8) * PS_STRIDE + ks * 8 + t    ]);
            pa[2] = __float_as_uint(Pw[(g    ) * PS_STRIDE + ks * 8 + t + 4]);
            pa[3] = __float_as_uint(Pw[(g + 8) * PS_STRIDE + ks * 8 + t + 4]);
            #pragma unroll
            for (int nb = 0; nb < 8; nb++) {
                uint32_t bf[2];
                bf[0] = __float_as_uint(Vsm[(ks * 8 + t    ) * VS_STRIDE + nb * 8 + g]);
                bf[1] = __float_as_uint(Vsm[(ks * 8 + t + 4) * VS_STRIDE + nb * 8 + g]);
                mma_tf32(O[nb], pa, bf);
            }
        }
        __syncwarp();
    }

    // Row-sum reduce across the 4-lane group, normalize, write out
    l0 += __shfl_xor_sync(0xffffffffu, l0, 1);
    l0 += __shfl_xor_sync(0xffffffffu, l0, 2);
    l1 += __shfl_xor_sync(0xffffffffu, l1, 1);
    l1 += __shfl_xor_sync(0xffffffffu, l1, 2);
    const float inv0 = 1.f / l0;
    const float inv1 = 1.f / l1;

    float* out0 = out + (size_t)(b * SEQ + rg    ) * CDIM + h * HDIM;
    float* out8 = out + (size_t)(b * SEQ + rg + 8) * CDIM + h * HDIM;
    #pragma unroll
    for (int nb = 0; nb < 8; nb++) {
        float2 v0 = { O[nb][0] * inv0, O[nb][1] * inv0 };
        float2 v1 = { O[nb][2] * inv1, O[nb][3] * inv1 };
        *(float2*)(out0 + nb * 8 + 2 * t) = v0;
        *(float2*)(out8 + nb * 8 + 2 * t) = v1;
    }
}

// ---------------------------------------------------------------------------
// Launch
// ---------------------------------------------------------------------------
extern "C" void kernel_launch(void* const* d_in, const int* in_sizes, int n_in,
                              void* d_out, int out_size)
{
    const float* x    = (const float*)d_in[0];
    const float* Wqkv = (const float*)d_in[1];
    const float* bqkv = (const float*)d_in[2];
    const float* Wout = (const float*)d_in[3];
    const float* bout = (const float*)d_in[4];
    float* out = (float*)d_out;

    float* qkv  = nullptr;
    float* attn = nullptr;
    cudaGetSymbolAddress((void**)&qkv,  g_qkv);
    cudaGetSymbolAddress((void**)&attn, g_attn);

    static bool attr_set = false;
    if (!attr_set) {
        cudaFuncSetAttribute(gemm_tc_kernel, cudaFuncAttributeMaxDynamicSharedMemorySize, GEMM_SMEM);
        cudaFuncSetAttribute(attn_tc_kernel, cudaFuncAttributeMaxDynamicSharedMemorySize, ATTN_SMEM);
        attr_set = true;
    }

    // 1) QKV projection: [4096,1024] @ [1024,3072] + bias
    {
        dim3 grid(C3 / GBN, MROWS / GBM);
        gemm_tc_kernel<<<grid, 256, GEMM_SMEM>>>(x, Wqkv, bqkv, qkv, MROWS, C3, CDIM);
    }
    // 2) Causal flash attention (tensor cores) -> g_attn [B,T,C]
    {
        dim3 grid(SEQ / AQ, NHEAD, BATCH);
        attn_tc_kernel<<<grid, 256, ATTN_SMEM>>>(qkv, attn);
    }
    // 3) Output projection: [4096,1024] @ [1024,1024] + bias -> d_out
    {
        dim3 grid(CDIM / GBN, MROWS / GBM);
        gemm_tc_kernel<<<grid, 256, GEMM_SMEM>>>(attn, Wout, bout, out, MROWS, CDIM, CDIM);
    }
}

// round 5
// speedup vs baseline: 4.2657x; 1.2598x over previous
#include <cuda_runtime.h>
#include <cuda_bf16.h>
#include <math.h>
#include <stdint.h>

// Problem constants
#define BATCH 2
#define SEQ   2048
#define CDIM  1024
#define NHEAD 16
#define HDIM  64
#define C3    (3*CDIM)          // 3072
#define MROWS (BATCH*SEQ)       // 4096

// Scratch (no cudaMalloc allowed)
__device__ float g_qkv[(size_t)MROWS * C3];       // [B,T,3,H,D] (tf32-rounded)
__device__ float g_attn[(size_t)MROWS * CDIM];    // [B,T,C]     (tf32-rounded)
__device__ float g_xr[(size_t)MROWS * CDIM];      // x, tf32-rounded
__device__ float g_wqkvr[(size_t)CDIM * C3];      // Wqkv, tf32-rounded
__device__ float g_woutr[(size_t)CDIM * CDIM];    // Wout, tf32-rounded

__device__ __forceinline__ uint32_t f2tf32(float f) {
    uint32_t r;
    asm("cvt.rna.tf32.f32 %0, %1;" : "=r"(r) : "f"(f));
    return r;
}
__device__ __forceinline__ float fexp2(float x) {
    float y;
    asm("ex2.approx.f32 %0, %1;" : "=f"(y) : "f"(x));
    return y;
}
__device__ __forceinline__ uint32_t smem_u32(const void* p) {
    uint32_t a;
    asm("{ .reg .u64 t; cvta.to.shared.u64 t, %1; cvt.u32.u64 %0, t; }" : "=r"(a) : "l"(p));
    return a;
}
#define CP_ASYNC16(dst_u32, src_ptr) \
    asm volatile("cp.async.cg.shared.global [%0], [%1], 16;" :: "r"(dst_u32), "l"(src_ptr) : "memory")
#define CP_COMMIT() asm volatile("cp.async.commit_group;" ::: "memory")
#define CP_WAIT0()  asm volatile("cp.async.wait_group 0;" ::: "memory")
#define CP_WAIT1()  asm volatile("cp.async.wait_group 1;" ::: "memory")
#define CP_WAIT2()  asm volatile("cp.async.wait_group 2;" ::: "memory")

__device__ __forceinline__ void mma_tf32(float c[4], const uint32_t a[4], const uint32_t b[2]) {
    asm volatile(
        "mma.sync.aligned.m16n8k8.row.col.f32.tf32.tf32.f32 "
        "{%0,%1,%2,%3}, {%4,%5,%6,%7}, {%8,%9}, {%0,%1,%2,%3};"
        : "+f"(c[0]), "+f"(c[1]), "+f"(c[2]), "+f"(c[3])
        : "r"(a[0]), "r"(a[1]), "r"(a[2]), "r"(a[3]), "r"(b[0]), "r"(b[1]));
}

// ---------------------------------------------------------------------------
// tf32 pre-round pass (memory-bound, ~GB/s limited)
// ---------------------------------------------------------------------------
__global__ __launch_bounds__(256)
void round_tf32_kernel(const float* __restrict__ in, float* __restrict__ out, int n4)
{
    int i = blockIdx.x * blockDim.x + threadIdx.x;
    if (i < n4) {
        float4 v = ((const float4*)in)[i];
        float4 o;
        o.x = __uint_as_float(f2tf32(v.x));
        o.y = __uint_as_float(f2tf32(v.y));
        o.z = __uint_as_float(f2tf32(v.z));
        o.w = __uint_as_float(f2tf32(v.w));
        ((float4*)out)[i] = o;
    }
}

// ---------------------------------------------------------------------------
// tf32 mma.sync GEMM + bias, cp.async 3-stage pipeline.
// C[M,N] = A[M,K] @ B[K,N] + bias[N]. A,B must be tf32-pre-rounded.
// CTA 128x128, BK=32, 8 warps (2x4), warp tile 64x32.
// RND: round outputs to tf32 (for intermediate tensors feeding later mma).
// ---------------------------------------------------------------------------
#define GBM 128
#define GBN 128
#define GBK 32
#define A_STRIDE 36
#define B_STRIDE 136
#define A_FLOATS (GBM * A_STRIDE)       // 4608
#define B_FLOATS (GBK * B_STRIDE)       // 4352
#define STG_FLOATS (A_FLOATS + B_FLOATS)
#define GEMM_SMEM (3 * STG_FLOATS * 4)  // 107520 B

template<bool RND>
__global__ __launch_bounds__(256)
void gemm_tc_kernel(const float* __restrict__ A,
                    const float* __restrict__ B,
                    const float* __restrict__ bias,
                    float* __restrict__ C,
                    int M, int N, int K)
{
    extern __shared__ float smem[];
    const int tid = threadIdx.x;
    const int wid = tid >> 5;
    const int l   = tid & 31;
    const int warpM = wid >> 2;
    const int warpN = wid & 3;
    const int rowbase = blockIdx.y * GBM;
    const int colbase = blockIdx.x * GBN;

    const uint32_t smb = smem_u32(smem);

    float acc[4][4][4];
    #pragma unroll
    for (int i = 0; i < 4; i++)
        #pragma unroll
        for (int j = 0; j < 4; j++)
            #pragma unroll
            for (int q = 0; q < 4; q++) acc[i][j][q] = 0.f;

    // cp.async mappings
    const int a_r = tid >> 3, a_c = (tid & 7) * 4;     // A: 128 rows x 8 chunks
    const int b_r = tid >> 5, b_c = (tid & 31) * 4;    // B: 32 rows x 32 chunks

    const int S = K / GBK;

    auto load_stage = [&](int stg, int k0) {
        const uint32_t sa = smb + stg * STG_FLOATS * 4;
        const uint32_t sb = sa + A_FLOATS * 4;
        #pragma unroll
        for (int it = 0; it < 4; it++) {
            const int r = it * 32 + a_r;
            CP_ASYNC16(sa + (uint32_t)(r * A_STRIDE + a_c) * 4,
                       A + (size_t)(rowbase + r) * K + k0 + a_c);
        }
        #pragma unroll
        for (int it = 0; it < 4; it++) {
            const int r = it * 8 + b_r;
            CP_ASYNC16(sb + (uint32_t)(r * B_STRIDE + b_c) * 4,
                       B + (size_t)(k0 + r) * N + colbase + b_c);
        }
        CP_COMMIT();
    };

    load_stage(0, 0);
    load_stage(1, GBK);

    const int arow0 = warpM * 64 + (l >> 2);
    const int bcol0 = warpN * 32 + (l >> 2);
    const int kfrag = (l & 3);

    for (int s = 0; s < S; s++) {
        if (s + 2 < S) { load_stage((s + 2) % 3, (s + 2) * GBK); CP_WAIT2(); }
        else if (s + 1 < S) { CP_WAIT1(); }
        else { CP_WAIT0(); }
        __syncthreads();

        const float* as = smem + (s % 3) * STG_FLOATS;
        const float* bs = as + A_FLOATS;
        #pragma unroll
        for (int ks = 0; ks < 4; ks++) {
            const int kk = ks * 8 + kfrag;
            uint32_t af[4][4], bf[4][2];
            #pragma unroll
            for (int i = 0; i < 4; i++) {
                const int r = arow0 + i * 16;
                af[i][0] = __float_as_uint(as[(r    ) * A_STRIDE + kk    ]);
                af[i][1] = __float_as_uint(as[(r + 8) * A_STRIDE + kk    ]);
                af[i][2] = __float_as_uint(as[(r    ) * A_STRIDE + kk + 4]);
                af[i][3] = __float_as_uint(as[(r + 8) * A_STRIDE + kk + 4]);
            }
            #pragma unroll
            for (int j = 0; j < 4; j++) {
                const int n = bcol0 + j * 8;
                bf[j][0] = __float_as_uint(bs[(ks * 8 + kfrag    ) * B_STRIDE + n]);
                bf[j][1] = __float_as_uint(bs[(ks * 8 + kfrag + 4) * B_STRIDE + n]);
            }
            #pragma unroll
            for (int i = 0; i < 4; i++)
                #pragma unroll
                for (int j = 0; j < 4; j++)
                    mma_tf32(acc[i][j], af[i], bf[j]);
        }
        __syncthreads();
    }

    const int erow = rowbase + warpM * 64 + (l >> 2);
    const int ecol = colbase + warpN * 32 + 2 * (l & 3);
    #pragma unroll
    for (int i = 0; i < 4; i++) {
        #pragma unroll
        for (int j = 0; j < 4; j++) {
            const int r0 = erow + i * 16;
            const int c0 = ecol + j * 8;
            const float b0 = bias[c0], b1 = bias[c0 + 1];
            float2 v0, v1;
            if (RND) {
                v0.x = __uint_as_float(f2tf32(acc[i][j][0] + b0));
                v0.y = __uint_as_float(f2tf32(acc[i][j][1] + b1));
                v1.x = __uint_as_float(f2tf32(acc[i][j][2] + b0));
                v1.y = __uint_as_float(f2tf32(acc[i][j][3] + b1));
            } else {
                v0.x = acc[i][j][0] + b0; v0.y = acc[i][j][1] + b1;
                v1.x = acc[i][j][2] + b0; v1.y = acc[i][j][3] + b1;
            }
            *(float2*)(C + (size_t)r0 * N + c0)       = v0;
            *(float2*)(C + (size_t)(r0 + 8) * N + c0) = v1;
        }
    }
}

// ---------------------------------------------------------------------------
// Tensor-core flash attention: cp.async double-buffered K/V, inputs pre-rounded.
// CTA = 128 q rows of one (b,h); 8 warps x 16 rows. K-tile = 64 keys.
// ---------------------------------------------------------------------------
#define AQ 128
#define AK 64
#define KS_STRIDE 68
#define VS_STRIDE 72
#define PS_STRIDE 68
#define KS_FLOATS (AK * KS_STRIDE)                 // 4352
#define VS_FLOATS (AK * VS_STRIDE)                 // 4608
#define KV_FLOATS (KS_FLOATS + VS_FLOATS)          // 8960 per stage
#define PS_FLOATS (8 * 16 * PS_STRIDE)             // 8704
#define ATTN_SMEM ((2 * KV_FLOATS + PS_FLOATS) * 4) // 106496 B

__global__ __launch_bounds__(256)
void attn_tc_kernel(const float* __restrict__ qkv, float* __restrict__ out)
{
    extern __shared__ float sm[];
    float* Psm = sm + 2 * KV_FLOATS;

    const int qtile = blockIdx.x;
    const int h   = blockIdx.y;
    const int b   = blockIdx.z;
    const int tid = threadIdx.x;
    const int wid = tid >> 5;
    const int l   = tid & 31;
    const int g   = l >> 2;
    const int t   = l & 3;
    const int qb  = qtile * AQ;
    const int rg  = qb + wid * 16 + g;

    const float SC = 0.18033688011112042f;   // (1/sqrt(64)) * log2(e)
    float* Pw = Psm + wid * (16 * PS_STRIDE);
    const uint32_t smb = smem_u32(sm);

    // cp.async K/V tile loader: r = idx/16, c = (idx%16)*4
    const int kv_r = tid >> 2;            // with 4 iters: rows 0..63 (it*? see below)
    const int kv_c = (tid & 3) * 16;      // 4 chunks of 16B per row quarter? (use flat mapping below)

    auto load_kv = [&](int stg, int kb) {
        const uint32_t kbuf = smb + stg * KV_FLOATS * 4;
        const uint32_t vbuf = kbuf + KS_FLOATS * 4;
        #pragma unroll
        for (int it = 0; it < 4; it++) {
            const int idx = it * 256 + tid;
            const int r = idx >> 4;
            const int c = (idx & 15) * 4;
            const float* src = qkv + (size_t)(b * SEQ + kb + r) * C3 + h * HDIM + c;
            CP_ASYNC16(kbuf + (uint32_t)(r * KS_STRIDE + c) * 4, src + CDIM);
            CP_ASYNC16(vbuf + (uint32_t)(r * VS_STRIDE + c) * 4, src + 2 * CDIM);
        }
        CP_COMMIT();
    };
    (void)kv_r; (void)kv_c;

    // Q fragments (pre-rounded tf32 bits), register-resident
    uint32_t qa[8][4];
    {
        const float* Qr  = qkv + (size_t)(b * SEQ + rg    ) * C3 + h * HDIM;
        const float* Qr8 = qkv + (size_t)(b * SEQ + rg + 8) * C3 + h * HDIM;
        #pragma unroll
        for (int ks = 0; ks < 8; ks++) {
            qa[ks][0] = __float_as_uint(Qr [ks * 8 + t]);
            qa[ks][1] = __float_as_uint(Qr8[ks * 8 + t]);
            qa[ks][2] = __float_as_uint(Qr [ks * 8 + t + 4]);
            qa[ks][3] = __float_as_uint(Qr8[ks * 8 + t + 4]);
        }
    }

    float O[8][4];
    #pragma unroll
    for (int nb = 0; nb < 8; nb++)
        #pragma unroll
        for (int q = 0; q < 4; q++) O[nb][q] = 0.f;
    float m0 = -INFINITY, m1 = -INFINITY, l0 = 0.f, l1 = 0.f;

    const int ntiles = (qb + AQ) / AK;

    load_kv(0, 0);

    for (int ti = 0; ti < ntiles; ti++) {
        if (ti + 1 < ntiles) { load_kv((ti + 1) & 1, (ti + 1) * AK); CP_WAIT1(); }
        else { CP_WAIT0(); }
        __syncthreads();

        const float* Ksm = sm + (ti & 1) * KV_FLOATS;
        const float* Vsm = Ksm + KS_FLOATS;
        const int kb = ti * AK;

        // S = Q @ K^T
        float sc[8][4];
        #pragma unroll
        for (int nb = 0; nb < 8; nb++) {
            sc[nb][0] = 0.f; sc[nb][1] = 0.f; sc[nb][2] = 0.f; sc[nb][3] = 0.f;
            #pragma unroll
            for (int ks = 0; ks < 8; ks++) {
                uint32_t bf[2];
                bf[0] = __float_as_uint(Ksm[(nb * 8 + g) * KS_STRIDE + ks * 8 + t    ]);
                bf[1] = __float_as_uint(Ksm[(nb * 8 + g) * KS_STRIDE + ks * 8 + t + 4]);
                mma_tf32(sc[nb], qa[ks], bf);
            }
        }

        float tm0 = -INFINITY, tm1 = -INFINITY;
        #pragma unroll
        for (int nb = 0; nb < 8; nb++) {
            const int k0 = kb + nb * 8 + 2 * t;
            float s0 = sc[nb][0] * SC, s1 = sc[nb][1] * SC;
            float s2 = sc[nb][2] * SC, s3 = sc[nb][3] * SC;
            if (k0     > rg    ) s0 = -INFINITY;
            if (k0 + 1 > rg    ) s1 = -INFINITY;
            if (k0     > rg + 8) s2 = -INFINITY;
            if (k0 + 1 > rg + 8) s3 = -INFINITY;
            sc[nb][0] = s0; sc[nb][1] = s1; sc[nb][2] = s2; sc[nb][3] = s3;
            tm0 = fmaxf(tm0, fmaxf(s0, s1));
            tm1 = fmaxf(tm1, fmaxf(s2, s3));
        }
        tm0 = fmaxf(tm0, __shfl_xor_sync(0xffffffffu, tm0, 1));
        tm0 = fmaxf(tm0, __shfl_xor_sync(0xffffffffu, tm0, 2));
        tm1 = fmaxf(tm1, __shfl_xor_sync(0xffffffffu, tm1, 1));
        tm1 = fmaxf(tm1, __shfl_xor_sync(0xffffffffu, tm1, 2));

        const float nm0 = fmaxf(m0, tm0);
        const float nm1 = fmaxf(m1, tm1);
        const float c0 = fexp2(m0 - nm0);
        const float c1 = fexp2(m1 - nm1);
        l0 *= c0; l1 *= c1;
        #pragma unroll
        for (int nb = 0; nb < 8; nb++) {
            O[nb][0] *= c0; O[nb][1] *= c0;
            O[nb][2] *= c1; O[nb][3] *= c1;
        }
        m0 = nm0; m1 = nm1;

        #pragma unroll
        for (int nb = 0; nb < 8; nb++) {
            float p0 = fexp2(sc[nb][0] - m0);
            float p1 = fexp2(sc[nb][1] - m0);
            float p2 = fexp2(sc[nb][2] - m1);
            float p3 = fexp2(sc[nb][3] - m1);
            l0 += p0 + p1;
            l1 += p2 + p3;
            uint2 u0 = { f2tf32(p0), f2tf32(p1) };
            uint2 u1 = { f2tf32(p2), f2tf32(p3) };
            *(uint2*)(Pw + (g    ) * PS_STRIDE + nb * 8 + 2 * t) = u0;
            *(uint2*)(Pw + (g + 8) * PS_STRIDE + nb * 8 + 2 * t) = u1;
        }
        __syncwarp();

        #pragma unroll
        for (int ks = 0; ks < 8; ks++) {
            uint32_t pa[4];
            pa[0] = __float_as_uint(Pw[(g    ) * PS_STRIDE + ks * 8 + t    ]);
            pa[1] = __float_as_uint(Pw[(g + 8) * PS_STRIDE + ks * 8 + t    ]);
            pa[2] = __float_as_uint(Pw[(g    ) * PS_STRIDE + ks * 8 + t + 4]);
            pa[3] = __float_as_uint(Pw[(g + 8) * PS_STRIDE + ks * 8 + t + 4]);
            #pragma unroll
            for (int nb = 0; nb < 8; nb++) {
                uint32_t bf[2];
                bf[0] = __float_as_uint(Vsm[(ks * 8 + t    ) * VS_STRIDE + nb * 8 + g]);
                bf[1] = __float_as_uint(Vsm[(ks * 8 + t + 4) * VS_STRIDE + nb * 8 + g]);
                mma_tf32(O[nb], pa, bf);
            }
        }
        __syncthreads();   // all warps done with this K/V buffer before reload
    }

    l0 += __shfl_xor_sync(0xffffffffu, l0, 1);
    l0 += __shfl_xor_sync(0xffffffffu, l0, 2);
    l1 += __shfl_xor_sync(0xffffffffu, l1, 1);
    l1 += __shfl_xor_sync(0xffffffffu, l1, 2);
    const float inv0 = 1.f / l0;
    const float inv1 = 1.f / l1;

    float* out0 = out + (size_t)(b * SEQ + rg    ) * CDIM + h * HDIM;
    float* out8 = out + (size_t)(b * SEQ + rg + 8) * CDIM + h * HDIM;
    #pragma unroll
    for (int nb = 0; nb < 8; nb++) {
        float2 v0, v1;
        v0.x = __uint_as_float(f2tf32(O[nb][0] * inv0));
        v0.y = __uint_as_float(f2tf32(O[nb][1] * inv0));
        v1.x = __uint_as_float(f2tf32(O[nb][2] * inv1));
        v1.y = __uint_as_float(f2tf32(O[nb][3] * inv1));
        *(float2*)(out0 + nb * 8 + 2 * t) = v0;
        *(float2*)(out8 + nb * 8 + 2 * t) = v1;
    }
}

// ---------------------------------------------------------------------------
// Launch
// ---------------------------------------------------------------------------
extern "C" void kernel_launch(void* const* d_in, const int* in_sizes, int n_in,
                              void* d_out, int out_size)
{
    const float* x    = (const float*)d_in[0];
    const float* Wqkv = (const float*)d_in[1];
    const float* bqkv = (const float*)d_in[2];
    const float* Wout = (const float*)d_in[3];
    const float* bout = (const float*)d_in[4];
    float* out = (float*)d_out;

    float *qkv, *attn, *xr, *wqkvr, *woutr;
    cudaGetSymbolAddress((void**)&qkv,   g_qkv);
    cudaGetSymbolAddress((void**)&attn,  g_attn);
    cudaGetSymbolAddress((void**)&xr,    g_xr);
    cudaGetSymbolAddress((void**)&wqkvr, g_wqkvr);
    cudaGetSymbolAddress((void**)&woutr, g_woutr);

    static bool attr_set = false;
    if (!attr_set) {
        cudaFuncSetAttribute(gemm_tc_kernel<true>,  cudaFuncAttributeMaxDynamicSharedMemorySize, GEMM_SMEM);
        cudaFuncSetAttribute(gemm_tc_kernel<false>, cudaFuncAttributeMaxDynamicSharedMemorySize, GEMM_SMEM);
        cudaFuncSetAttribute(attn_tc_kernel, cudaFuncAttributeMaxDynamicSharedMemorySize, ATTN_SMEM);
        attr_set = true;
    }

    // 0) Pre-round GEMM operands to tf32
    round_tf32_kernel<<<(MROWS * CDIM / 4 + 255) / 256, 256>>>(x,    xr,    MROWS * CDIM / 4);
    round_tf32_kernel<<<(CDIM * C3 / 4 + 255) / 256, 256>>>(Wqkv, wqkvr, CDIM * C3 / 4);
    round_tf32_kernel<<<(CDIM * CDIM / 4 + 255) / 256, 256>>>(Wout, woutr, CDIM * CDIM / 4);

    // 1) QKV projection (round outputs -> attention operands pre-rounded)
    {
        dim3 grid(C3 / GBN, MROWS / GBM);
        gemm_tc_kernel<true><<<grid, 256, GEMM_SMEM>>>(xr, wqkvr, bqkv, qkv, MROWS, C3, CDIM);
    }
    // 2) Causal flash attention (tensor cores) -> g_attn (tf32-rounded)
    {
        dim3 grid(SEQ / AQ, NHEAD, BATCH);
        attn_tc_kernel<<<grid, 256, ATTN_SMEM>>>(qkv, attn);
    }
    // 3) Output projection (fp32 output)
    {
        dim3 grid(CDIM / GBN, MROWS / GBM);
        gemm_tc_kernel<false><<<grid, 256, GEMM_SMEM>>>(attn, woutr, bout, out, MROWS, CDIM, CDIM);
    }
}